// round 13
// baseline (speedup 1.0000x reference)
#include <cuda_runtime.h>
#include <cstdint>

// Problem constants (fixed shapes per reference)
#define C_DIM   1024
#define H_DIM   128
#define W_DIM   128
#define NROIS   256
#define NPATCH_TOT 1024                // 4 patches * 256 rois
#define THREADS 256
#define SEGS    8                      // one 16-row segment per warp
#define SEG_H   (H_DIM / SEGS)         // 16

// Dynamic smem: tile (128*128, segment-local SAT) + cum (8*128 seg bases)
#define SMEM_FLOATS (H_DIM * W_DIM + SEGS * W_DIM)
#define SMEM_BYTES  (SMEM_FLOATS * (int)sizeof(float))

// Channel-major intermediate: tmp[c][n]. Static device scratch (no allocs).
__device__ float g_tmp[C_DIM * NPATCH_TOT];

__global__ __launch_bounds__(THREADS, 3)
void roi_pool_sat_kernel(const float* __restrict__ fm,
                         const float* __restrict__ roi) {
    extern __shared__ float smem[];
    float* tile = smem;                  // [H][W]: segment-local 2-D SAT
    float* cum  = smem + H_DIM * W_DIM;  // [SEGS][W]: totals -> excl. bases

    const int tid  = threadIdx.x;
    const int lane = tid & 31;
    const int warp = tid >> 5;           // segment id, rows [16w, 16w+16)
    const int c    = blockIdx.x;

    // ---- Per-thread ROI -> shared 3x3 corner grid, in registers ----
    // Thread tid owns ROI r = tid. Match JAX op order exactly:
    // wstep = (xmax-xmin)/2 (exact halving), x_i = round(xmin + i*wstep),
    // rn ops, no FMA contraction. rintf == jnp.round (half-to-even).
    int X[3], Y[3];
    {
        const float4 rb = reinterpret_cast<const float4*>(roi)[tid];
        const float wstep = __fmul_rn(__fadd_rn(rb.z, -rb.x), 0.5f);
        const float hstep = __fmul_rn(__fadd_rn(rb.w, -rb.y), 0.5f);
        const float ax1 = __fadd_rn(rb.x, wstep);
        const float ay1 = __fadd_rn(rb.y, hstep);
        X[0] = (int)rintf(rb.x);
        X[1] = (int)rintf(ax1);
        X[2] = (int)rintf(__fadd_rn(ax1, wstep));
        Y[0] = (int)rintf(rb.y);
        Y[1] = (int)rintf(ay1);
        Y[2] = (int)rintf(__fadd_rn(ay1, hstep));
    }

    const float* plane = fm + (size_t)c * (H_DIM * W_DIM);

    // ---- Fused row-scan + column accumulation (segment-local 2-D SAT) ----
    // Warp w processes its 16 rows in order. For each row: shuffle-based
    // row prefix, then colacc += rowprefix, store colacc. tile is written
    // ONCE; no separate column-scan smem phase. Loads across rows are
    // independent (ptxas hoists -> deep MLP during the DRAM-bound phase).
    {
        float4 cc = make_float4(0.0f, 0.0f, 0.0f, 0.0f);   // per-lane col sums
        #pragma unroll
        for (int j = 0; j < SEG_H; j++) {
            const int h = warp * SEG_H + j;
            float4 v = reinterpret_cast<const float4*>(plane + h * W_DIM)[lane];
            float s0 = v.x;
            float s1 = s0 + v.y;
            float s2 = s1 + v.z;
            float s3 = s2 + v.w;
            float x = s3;
            #pragma unroll
            for (int off = 1; off < 32; off <<= 1) {
                float y = __shfl_up_sync(0xffffffffu, x, off);
                if (lane >= off) x += y;
            }
            const float e = x - s3;     // exclusive prefix of lane's chunk
            cc.x += e + s0;
            cc.y += e + s1;
            cc.z += e + s2;
            cc.w += e + s3;
            reinterpret_cast<float4*>(tile + h * W_DIM)[lane] = cc;
        }
        // Segment column totals (= colacc after last row)
        reinterpret_cast<float4*>(cum + warp * W_DIM)[lane] = cc;
    }
    __syncthreads();

    // ---- Exclusive scan of segment totals per column ----
    if (tid < W_DIM) {
        float run = 0.0f;
        #pragma unroll
        for (int s = 0; s < SEGS; s++) {
            const float t = cum[s * W_DIM + tid];
            cum[s * W_DIM + tid] = run;
            run += t;
        }
    }
    __syncthreads();

    // ---- Gather: 3x3 shared SAT corner grid per ROI ----
    // SAT(y,x) = tile[y][x] + cum[y>>4][x]; A[j][i] = SAT(Y[j]-1, X[i]-1).
    float A[3][3];
    #pragma unroll
    for (int j = 0; j < 3; j++) {
        #pragma unroll
        for (int i = 0; i < 3; i++) {
            const int y = Y[j] - 1;
            const int x = X[i] - 1;
            float v = 0.0f;
            if (y >= 0 && x >= 0)
                v = tile[y * W_DIM + x] + cum[(y >> 4) * W_DIM + x];
            A[j][i] = v;
        }
    }

    // patch pi = iy*2 + ix ; n = pi*NROIS + tid (reference reshape order)
    float* dst = g_tmp + (size_t)c * NPATCH_TOT + tid;
    #pragma unroll
    for (int iy = 0; iy < 2; iy++) {
        #pragma unroll
        for (int ix = 0; ix < 2; ix++) {
            const float s = (A[iy + 1][ix + 1] - A[iy][ix + 1])
                          - (A[iy + 1][ix]     - A[iy][ix]);
            const float cnt = (float)((Y[iy + 1] - Y[iy]) * (X[ix + 1] - X[ix]));
            dst[(iy * 2 + ix) * NROIS] = s / fmaxf(cnt, 1.0f);
        }
    }
}

// ---- Transpose g_tmp[c][n] -> out[n][c] ----
// 4 independent 32x32 tiles per block: 16 LDG in flight per thread, one
// barrier, 16 STG. 256 blocks. (R6 profile: old version was block-serial
// L2-latency bound — issue 19.6%, DRAM 10.5%.)
#define TT 4   // tiles per block (along n)
__global__ __launch_bounds__(256)
void transpose_kernel(float* __restrict__ out) {
    __shared__ float t[TT][32][33];
    const int bx = blockIdx.x * (32 * TT);  // n origin of tile group
    const int by = blockIdx.y * 32;         // c origin
    const int tx = threadIdx.x;             // 0..31
    const int ty = threadIdx.y;             // 0..7

    #pragma unroll
    for (int s = 0; s < TT; s++) {
        #pragma unroll
        for (int j = 0; j < 32; j += 8)
            t[s][ty + j][tx] =
                g_tmp[(size_t)(by + ty + j) * NPATCH_TOT + (bx + s * 32 + tx)];
    }
    __syncthreads();
    #pragma unroll
    for (int s = 0; s < TT; s++) {
        #pragma unroll
        for (int j = 0; j < 32; j += 8)
            out[(size_t)(bx + s * 32 + ty + j) * C_DIM + (by + tx)] =
                t[s][tx][ty + j];
    }
}

extern "C" void kernel_launch(void* const* d_in, const int* in_sizes, int n_in,
                              void* d_out, int out_size) {
    (void)in_sizes; (void)n_in; (void)out_size;
    const float* fm  = (const float*)d_in[0];   // feature_map (1024,128,128) f32
    const float* roi = (const float*)d_in[1];   // roi_batch (256,4) f32
    float* out = (float*)d_out;                 // (1024, 1024, 1, 1) f32

    // Host-side attrs (idempotent, not stream ops -> capture-safe).
    // Carveout 100%: guarantee 3 x 69.6 KB blocks/SM.
    cudaFuncSetAttribute(roi_pool_sat_kernel,
                         cudaFuncAttributeMaxDynamicSharedMemorySize, SMEM_BYTES);
    cudaFuncSetAttribute(roi_pool_sat_kernel,
                         cudaFuncAttributePreferredSharedMemoryCarveout, 100);

    roi_pool_sat_kernel<<<C_DIM, THREADS, SMEM_BYTES>>>(fm, roi);

    dim3 tgrid(NPATCH_TOT / (32 * TT), C_DIM / 32);
    dim3 tblk(32, 8);
    transpose_kernel<<<tgrid, tblk>>>(out);
}